// round 7
// baseline (speedup 1.0000x reference)
#include <cuda_runtime.h>
#include <mma.h>

using namespace nvcuda;

#define PB 2
#define PS 2048
#define PD 1024
#define PH 16
#define PHD 64

// Scratch (__device__ globals; no allocation allowed)
__device__ float g_qkv[(size_t)PB * PS * 3 * PD];          // [4096, 3072]
__device__ float g_y[(size_t)PB * PS * PD];                // attention out [B,S,D]
__device__ float g_invL[(size_t)PB * PH * PS];             // per-row 1/sumexp
__device__ float g_att_scratch[(size_t)PB * PH * PS * PS]; // fallback if att not in d_out

// ---------------------------------------------------------------------------
// tf32 split helpers (3xTF32: value = hi + lo, both tf32-representable)
// ---------------------------------------------------------------------------
__device__ __forceinline__ void tf32_split(float x, float& hi, float& lo) {
    hi = wmma::__float_to_tf32(x);
    lo = wmma::__float_to_tf32(x - hi);
}

// cp.async helpers
__device__ __forceinline__ void cp16(void* smem, const void* gmem) {
    unsigned s = (unsigned)__cvta_generic_to_shared(smem);
    asm volatile("cp.async.cg.shared.global [%0], [%1], 16;\n" :: "r"(s), "l"(gmem));
}
#define CP_COMMIT() asm volatile("cp.async.commit_group;\n" ::: "memory")

// ---------------------------------------------------------------------------
// gemm128: C[M,N] = A[M,K] @ B[N,K]^T   (row-major, 3xTF32 WMMA, fp32 acc)
// Tiles 128x128x32, 256 threads, 3-stage cp.async pipeline (dynamic smem).
// Stage layout (floats): [stage][ As 128x36 | Bs 128x36 ]  stride 9216
// Total: 3 * 9216 * 4B = 110592 bytes -> 2 CTAs/SM.
// Group accounting: prologue commits stages 0,1; every iteration commits
// exactly one group (possibly empty), so at iter kt after the commit there
// are (3+kt) groups total and stage kt is complete once <=2 are outstanding.
// ---------------------------------------------------------------------------
#define GM_STAGE_FLOATS 9216
#define GM_B_OFF        4608
#define GM_SMEM_BYTES   110592

__device__ __forceinline__ void stage32(float (*dst)[36], const float* g,
                                        long long ld, int tid) {
    #pragma unroll
    for (int i = 0; i < 4; i++) {
        int id  = tid + 256 * i;      // 1024 slots: 128 rows x 8 segs
        int row = id >> 3, seg = id & 7;
        cp16(&dst[row][seg * 4], g + (long long)row * ld + seg * 4);
    }
}

__global__ __launch_bounds__(256)
void gemm128(const float* __restrict__ A, const float* __restrict__ B,
             float* __restrict__ C, int M, int N, int K)
{
    extern __shared__ float gsm[];

    const int tid  = threadIdx.x;
    const int warp = tid >> 5;
    const int bm   = blockIdx.y * 128;
    const int bn   = blockIdx.x * 128;
    const int wm   = (warp >> 1) * 32;   // 4 warps in m
    const int wn   = (warp & 1) * 64;    // 2 warps in n

    const float* gA = A + (long long)bm * K;
    const float* gB = B + (long long)bn * K;

    wmma::fragment<wmma::accumulator, 16, 16, 8, float> acc[2][4];
    #pragma unroll
    for (int i = 0; i < 2; i++)
        #pragma unroll
        for (int j = 0; j < 4; j++)
            wmma::fill_fragment(acc[i][j], 0.0f);

    const int KT = K >> 5;               // BK = 32

    // Prologue: stages 0 and 1, one commit group each
    #pragma unroll
    for (int s = 0; s < 2; s++) {
        if (s < KT) {
            float (*As)[36] = (float(*)[36])(gsm + s * GM_STAGE_FLOATS);
            float (*Bs)[36] = (float(*)[36])(gsm + s * GM_STAGE_FLOATS + GM_B_OFF);
            stage32(As, gA + (long long)s * 32, K, tid);
            stage32(Bs, gB + (long long)s * 32, K, tid);
        }
        CP_COMMIT();
    }

    for (int kt = 0; kt < KT; kt++) {
        // Prefetch stage kt+2 into buffer (kt+2)%3; always commit one group.
        if (kt + 2 < KT) {
            int buf = (kt + 2) % 3;
            float (*As)[36] = (float(*)[36])(gsm + buf * GM_STAGE_FLOATS);
            float (*Bs)[36] = (float(*)[36])(gsm + buf * GM_STAGE_FLOATS + GM_B_OFF);
            stage32(As, gA + (long long)(kt + 2) * 32, K, tid);
            stage32(Bs, gB + (long long)(kt + 2) * 32, K, tid);
        }
        CP_COMMIT();
        // Groups committed: 3+kt. Stage kt complete when <=2 outstanding.
        asm volatile("cp.async.wait_group 2;\n" ::: "memory");
        __syncthreads();

        const int cur = kt % 3;
        float (*As)[36] = (float(*)[36])(gsm + cur * GM_STAGE_FLOATS);
        float (*Bs)[36] = (float(*)[36])(gsm + cur * GM_STAGE_FLOATS + GM_B_OFF);

        #pragma unroll
        for (int kk = 0; kk < 32; kk += 8) {
            wmma::fragment<wmma::matrix_a, 16, 16, 8, wmma::precision::tf32, wmma::row_major> aHi[2], aLo[2];
            wmma::fragment<wmma::matrix_b, 16, 16, 8, wmma::precision::tf32, wmma::col_major> bHi[4], bLo[4];
            #pragma unroll
            for (int i = 0; i < 2; i++) {
                wmma::load_matrix_sync(aHi[i], &As[wm + 16 * i][kk], 36);
                #pragma unroll
                for (int t = 0; t < aHi[i].num_elements; t++) {
                    float hi, lo; tf32_split(aHi[i].x[t], hi, lo);
                    aHi[i].x[t] = hi; aLo[i].x[t] = lo;
                }
            }
            #pragma unroll
            for (int j = 0; j < 4; j++) {
                wmma::load_matrix_sync(bHi[j], &Bs[wn + 16 * j][kk], 36);
                #pragma unroll
                for (int t = 0; t < bHi[j].num_elements; t++) {
                    float hi, lo; tf32_split(bHi[j].x[t], hi, lo);
                    bHi[j].x[t] = hi; bLo[j].x[t] = lo;
                }
            }
            #pragma unroll
            for (int i = 0; i < 2; i++)
                #pragma unroll
                for (int j = 0; j < 4; j++) {
                    wmma::mma_sync(acc[i][j], aHi[i], bLo[j], acc[i][j]);
                    wmma::mma_sync(acc[i][j], aLo[i], bHi[j], acc[i][j]);
                    wmma::mma_sync(acc[i][j], aHi[i], bHi[j], acc[i][j]);
                }
        }
        __syncthreads();
    }

    #pragma unroll
    for (int i = 0; i < 2; i++)
        #pragma unroll
        for (int j = 0; j < 4; j++)
            wmma::store_matrix_sync(&C[(long long)(bm + wm + 16 * i) * N + bn + wn + 16 * j],
                                    acc[i][j], N, wmma::mem_row_major);
}

// ---------------------------------------------------------------------------
// Single-pass flash attention (max-free: scores bounded, exp can't overflow).
// Per CTA: 128 q-rows of one (b,h); K/V tiles 64 wide, cp.async double-buffered.
// 512 threads, 16 warps, warp tile 16x32.
// Writes UNNORMALIZED p=exp(s) to att, accumulates L=sum(p) and y'=p@V;
// epilogue writes y = y'/L (directly in [B,S,D]) and 1/L.
// Dynamic smem layout (floats):
//   Qs  [128][68]     @ 0       (8704)
//   Ss  [128][68]     @ 8704    (8704)
//   Ks  [2][64][68]   @ 17408   (8704)
//   Vs  [2][64][68]   @ 26112   (8704)
//   Lrow[128]         @ 34816
// total 34944 floats = 139776 bytes
// ---------------------------------------------------------------------------
#define FL_LD 68
#define FL_Q  0
#define FL_S  8704
#define FL_K  17408
#define FL_V  26112
#define FL_L  34816
#define FL_SMEM_BYTES 139776
#define FL_THREADS 512

__global__ __launch_bounds__(FL_THREADS)
void attn_flash(const float* __restrict__ qkv,
                float* __restrict__ att, float* __restrict__ y,
                float* __restrict__ invLout)
{
    extern __shared__ float sm[];
    float* Qs   = sm + FL_Q;
    float* Ss   = sm + FL_S;
    float* Lrow = sm + FL_L;

    const int tid = threadIdx.x, warp = tid >> 5, lane = tid & 31;
    const int bh = blockIdx.y, b = bh >> 4, h = bh & 15;
    const int s0 = blockIdx.x * 128;

    const float* Qbase = qkv + ((long long)(b * PS + s0)) * (3 * PD) + h * PHD;
    const float* Kbase = qkv + ((long long)b * PS) * (3 * PD) + PD + h * PHD;
    const float* Vbase = qkv + ((long long)b * PS) * (3 * PD) + 2 * PD + h * PHD;

    if (tid < 128) Lrow[tid] = 0.0f;

    // Q tile 128x64, pre-scaled by 1/8 (exact power of 2)
    #pragma unroll
    for (int i = 0; i < 4; i++) {
        int id = tid + FL_THREADS * i;   // 2048 slots: 128 rows x 16 float4 segs
        int r = id >> 4, c4 = (id & 15) * 4;
        float4 v = *(const float4*)(Qbase + (long long)r * (3 * PD) + c4);
        v.x *= 0.125f; v.y *= 0.125f; v.z *= 0.125f; v.w *= 0.125f;
        *(float4*)&Qs[r * FL_LD + c4] = v;
    }

    // Stage K/V tile 0 (64 rows x 64 floats each -> 1024 float4 slots each)
    {
        float* K0 = sm + FL_K;
        float* V0 = sm + FL_V;
        #pragma unroll
        for (int i = 0; i < 2; i++) {
            int id = tid + FL_THREADS * i;
            int r = id >> 4, c4 = (id & 15) * 4;
            cp16(&K0[r * FL_LD + c4], Kbase + (long long)r * (3 * PD) + c4);
        }
        #pragma unroll
        for (int i = 0; i < 2; i++) {
            int id = tid + FL_THREADS * i;
            int r = id >> 4, c4 = (id & 15) * 4;
            cp16(&V0[r * FL_LD + c4], Vbase + (long long)r * (3 * PD) + c4);
        }
        CP_COMMIT();
    }

    const int wm = (warp >> 1) * 16;       // 8 row groups (128 rows)
    const int wn = (warp & 1) * 32;        // 2 col groups (64 cols)
    wmma::fragment<wmma::accumulator, 16, 16, 8, float> accY[2];
    wmma::fill_fragment(accY[0], 0.0f);
    wmma::fill_fragment(accY[1], 0.0f);

    const int pr  = tid >> 2;              // owned p-row (0..127)
    const int pc0 = (tid & 3) * 16;        // first of 16 owned cols
    const size_t attRow0 = (size_t)bh * PS + s0;

    const int NT = PS / 64;                // 32 iterations
    for (int nt = 0; nt < NT; nt++) {
        const int cur = nt & 1;
        float* Kc = sm + FL_K + cur * (64 * FL_LD);
        float* Vc = sm + FL_V + cur * (64 * FL_LD);

        if (nt + 1 < NT) {
            float* Kn = sm + FL_K + (cur ^ 1) * (64 * FL_LD);
            float* Vn = sm + FL_V + (cur ^ 1) * (64 * FL_LD);
            const float* Kg = Kbase + (long long)(nt + 1) * 64 * (3 * PD);
            const float* Vg = Vbase + (long long)(nt + 1) * 64 * (3 * PD);
            #pragma unroll
            for (int i = 0; i < 2; i++) {
                int id = tid + FL_THREADS * i;
                int r = id >> 4, c4 = (id & 15) * 4;
                cp16(&Kn[r * FL_LD + c4], Kg + (long long)r * (3 * PD) + c4);
            }
            #pragma unroll
            for (int i = 0; i < 2; i++) {
                int id = tid + FL_THREADS * i;
                int r = id >> 4, c4 = (id & 15) * 4;
                cp16(&Vn[r * FL_LD + c4], Vg + (long long)r * (3 * PD) + c4);
            }
            CP_COMMIT();
            asm volatile("cp.async.wait_group 1;\n" ::: "memory");
        } else {
            asm volatile("cp.async.wait_group 0;\n" ::: "memory");
        }
        __syncthreads();

        // scores 128x64 = (Q/8) @ K^T  (3xTF32); warp does 16x32
        {
            wmma::fragment<wmma::accumulator, 16, 16, 8, float> accS[2];
            wmma::fill_fragment(accS[0], 0.0f);
            wmma::fill_fragment(accS[1], 0.0f);
            #pragma unroll
            for (int kk = 0; kk < 64; kk += 8) {
                wmma::fragment<wmma::matrix_a, 16, 16, 8, wmma::precision::tf32, wmma::row_major> aHi, aLo;
                wmma::load_matrix_sync(aHi, &Qs[wm * FL_LD + kk], FL_LD);
                #pragma unroll
                for (int t = 0; t < aHi.num_elements; t++) {
                    float hi, lo; tf32_split(aHi.x[t], hi, lo);
                    aHi.x[t] = hi; aLo.x[t] = lo;
                }
                #pragma unroll
                for (int j = 0; j < 2; j++) {
                    wmma::fragment<wmma::matrix_b, 16, 16, 8, wmma::precision::tf32, wmma::col_major> bHi, bLo;
                    wmma::load_matrix_sync(bHi, &Kc[(wn + 16 * j) * FL_LD + kk], FL_LD);
                    #pragma unroll
                    for (int t = 0; t < bHi.num_elements; t++) {
                        float hi, lo; tf32_split(bHi.x[t], hi, lo);
                        bHi.x[t] = hi; bLo.x[t] = lo;
                    }
                    wmma::mma_sync(accS[j], aHi, bLo, accS[j]);
                    wmma::mma_sync(accS[j], aLo, bHi, accS[j]);
                    wmma::mma_sync(accS[j], aHi, bHi, accS[j]);
                }
            }
            wmma::store_matrix_sync(&Ss[wm * FL_LD + wn],      accS[0], FL_LD, wmma::mem_row_major);
            wmma::store_matrix_sync(&Ss[wm * FL_LD + wn + 16], accS[1], FL_LD, wmma::mem_row_major);
        }
        __syncthreads();

        // p = exp(s); write unnormalized att; accumulate row sums
        {
            const int n0 = nt * 64;
            float pv[16];
            float sum = 0.0f;
            #pragma unroll
            for (int t = 0; t < 16; t++) {
                pv[t] = __expf(Ss[pr * FL_LD + pc0 + t]);
                sum += pv[t];
            }
            #pragma unroll
            for (int t = 0; t < 16; t++) Ss[pr * FL_LD + pc0 + t] = pv[t];

            float4* dst = (float4*)(att + (attRow0 + pr) * PS + n0 + pc0);
            #pragma unroll
            for (int q = 0; q < 4; q++)
                dst[q] = make_float4(pv[4 * q], pv[4 * q + 1], pv[4 * q + 2], pv[4 * q + 3]);

            sum += __shfl_xor_sync(0xffffffffu, sum, 1);
            sum += __shfl_xor_sync(0xffffffffu, sum, 2);
            if ((lane & 3) == 0) Lrow[pr] += sum;   // unique thread per row
        }
        __syncthreads();

        // y' += p @ V   (3xTF32; M=128,N=64,K=64); warp does 16x32
        #pragma unroll
        for (int kk = 0; kk < 64; kk += 8) {
            wmma::fragment<wmma::matrix_a, 16, 16, 8, wmma::precision::tf32, wmma::row_major> aHi, aLo;
            wmma::load_matrix_sync(aHi, &Ss[wm * FL_LD + kk], FL_LD);
            #pragma unroll
            for (int t = 0; t < aHi.num_elements; t++) {
                float hi, lo; tf32_split(aHi.x[t], hi, lo);
                aHi.x[t] = hi; aLo.x[t] = lo;
            }
            #pragma unroll
            for (int j = 0; j < 2; j++) {
                wmma::fragment<wmma::matrix_b, 16, 16, 8, wmma::precision::tf32, wmma::row_major> bHi, bLo;
                wmma::load_matrix_sync(bHi, &Vc[kk * FL_LD + wn + 16 * j], FL_LD);
                #pragma unroll
                for (int t = 0; t < bHi.num_elements; t++) {
                    float hi, lo; tf32_split(bHi.x[t], hi, lo);
                    bHi.x[t] = hi; bLo.x[t] = lo;
                }
                wmma::mma_sync(accY[j], aHi, bLo, accY[j]);
                wmma::mma_sync(accY[j], aLo, bHi, accY[j]);
                wmma::mma_sync(accY[j], aHi, bHi, accY[j]);
            }
        }
        __syncthreads();
    }

    // Epilogue: y' -> smem (reuse Qs), scale by 1/L, write y in [B,S,D]
    wmma::store_matrix_sync(&Qs[wm * FL_LD + wn],      accY[0], FL_LD, wmma::mem_row_major);
    wmma::store_matrix_sync(&Qs[wm * FL_LD + wn + 16], accY[1], FL_LD, wmma::mem_row_major);
    __syncthreads();

    if (tid < 128) invLout[attRow0 + tid] = 1.0f / Lrow[tid];

    {
        const int r = tid >> 2, c0 = (tid & 3) * 16;
        const float inv = 1.0f / Lrow[r];
        float* ydst = y + ((long long)(b * PS + s0 + r)) * PD + h * PHD + c0;
        #pragma unroll
        for (int q = 0; q < 4; q++) {
            float4 v = *(float4*)&Qs[r * FL_LD + c0 + q * 4];
            v.x *= inv; v.y *= inv; v.z *= inv; v.w *= inv;
            *(float4*)(ydst + q * 4) = v;
        }
    }
}

// ---------------------------------------------------------------------------
// att fixup: scale each row of att by its 1/L. One block per row.
// ---------------------------------------------------------------------------
__global__ __launch_bounds__(512)
void att_scale(float* __restrict__ att, const float* __restrict__ invL)
{
    const size_t row = blockIdx.x;
    const float s = invL[row];
    float4* p = (float4*)(att + row * PS);
    float4 v = p[threadIdx.x];
    v.x *= s; v.y *= s; v.z *= s; v.w *= s;
    p[threadIdx.x] = v;
}

__global__ __launch_bounds__(256)
void add_bias(float* __restrict__ y, const float* __restrict__ bias, long long n)
{
    long long i = (long long)blockIdx.x * blockDim.x + threadIdx.x;
    if (i < n) y[i] += bias[i & (PD - 1)];
}

// ---------------------------------------------------------------------------
extern "C" void kernel_launch(void* const* d_in, const int* in_sizes, int n_in,
                              void* d_out, int out_size)
{
    const float* x     = (const float*)d_in[0];   // [B,S,D]
    const float* Wattn = (const float*)d_in[1];   // [3D, D]
    const float* Wproj = (const float*)d_in[2];   // [D, D]
    const float* bproj = (const float*)d_in[3];   // [D]
    float* out = (float*)d_out;

    float *qkv, *yb, *invL;
    cudaGetSymbolAddress((void**)&qkv,  g_qkv);
    cudaGetSymbolAddress((void**)&yb,   g_y);
    cudaGetSymbolAddress((void**)&invL, g_invL);

    const long long yElems   = (long long)PB * PS * PD;        // 4,194,304
    const long long attElems = (long long)PB * PH * PS * PS;   // 134,217,728

    float* attOut;
    if ((long long)out_size >= yElems + attElems) {
        attOut = out + yElems;                                 // (y, att) concat
    } else {
        cudaGetSymbolAddress((void**)&attOut, g_att_scratch);
    }

    cudaFuncSetAttribute(gemm128, cudaFuncAttributeMaxDynamicSharedMemorySize,
                         GM_SMEM_BYTES);
    cudaFuncSetAttribute(attn_flash, cudaFuncAttributeMaxDynamicSharedMemorySize,
                         FL_SMEM_BYTES);

    // 1) qkv = x @ W_attn^T : [4096, 3072]
    gemm128<<<dim3(3 * PD / 128, PB * PS / 128), 256, GM_SMEM_BYTES>>>(
        x, Wattn, qkv, PB * PS, 3 * PD, PD);

    // 2) flash: unnormalized att + L + y = (p@V)/L  (y in [B,S,D])
    attn_flash<<<dim3(PS / 128, PB * PH), FL_THREADS, FL_SMEM_BYTES>>>(qkv, attOut, yb, invL);

    // 3) normalize att rows
    att_scale<<<PB * PH * PS, 512>>>(attOut, invL);

    // 4) out_y = y @ W_proj^T
    gemm128<<<dim3(PD / 128, PB * PS / 128), 256, GM_SMEM_BYTES>>>(
        yb, Wproj, out, PB * PS, PD, PD);

    // 5) + b_proj
    add_bias<<<(unsigned)((yElems + 255) / 256), 256>>>(out, bproj, yElems);
}

// round 9
// speedup vs baseline: 2.1676x; 2.1676x over previous
#include <cuda_runtime.h>
#include <cuda_bf16.h>
#include <mma.h>

using namespace nvcuda;
typedef __nv_bfloat16 bf16;

#define PB 2
#define PS 2048
#define PD 1024
#define PH 16
#define PHD 64

// ---------------------------------------------------------------------------
// Scratch (__device__ globals; no allocation allowed)
// ---------------------------------------------------------------------------
__device__ float g_qkv [(size_t)PB * PS * 3 * PD];          // fp32 qkv
__device__ bf16  g_xhi [(size_t)PB * PS * PD];
__device__ bf16  g_xlo [(size_t)PB * PS * PD];
__device__ bf16  g_Wahi[(size_t)3 * PD * PD];
__device__ bf16  g_Walo[(size_t)3 * PD * PD];
__device__ bf16  g_Wphi[(size_t)PD * PD];
__device__ bf16  g_Wplo[(size_t)PD * PD];
__device__ bf16  g_qkvhi[(size_t)PB * PS * 3 * PD];
__device__ bf16  g_qkvlo[(size_t)PB * PS * 3 * PD];
__device__ bf16  g_yhi [(size_t)PB * PS * PD];
__device__ bf16  g_ylo [(size_t)PB * PS * PD];
__device__ float g_invL[(size_t)PB * PH * PS];
__device__ float g_att_scratch[(size_t)PB * PH * PS * PS];  // fallback

// cp.async helpers
__device__ __forceinline__ void cp16(void* smem, const void* gmem) {
    unsigned s = (unsigned)__cvta_generic_to_shared(smem);
    asm volatile("cp.async.cg.shared.global [%0], [%1], 16;\n" :: "r"(s), "l"(gmem));
}
#define CP_COMMIT() asm volatile("cp.async.commit_group;\n" ::: "memory")

__device__ __forceinline__ void split2(float x, bf16& hi, bf16& lo) {
    hi = __float2bfloat16_rn(x);
    lo = __float2bfloat16_rn(x - __bfloat162float(hi));
}

// ---------------------------------------------------------------------------
// split_bf16: fp32 -> (hi, lo) bf16 arrays. n must be a multiple of 4.
// ---------------------------------------------------------------------------
__global__ __launch_bounds__(256)
void split_bf16(const float* __restrict__ src, bf16* __restrict__ hi,
                bf16* __restrict__ lo, long long n)
{
    long long i = ((long long)blockIdx.x * 256 + threadIdx.x) * 4;
    if (i >= n) return;
    float4 v = *(const float4*)(src + i);
    bf16 h0, l0, h1, l1, h2, l2, h3, l3;
    split2(v.x, h0, l0); split2(v.y, h1, l1);
    split2(v.z, h2, l2); split2(v.w, h3, l3);
    __nv_bfloat162 ph0; ph0.x = h0; ph0.y = h1;
    __nv_bfloat162 ph1; ph1.x = h2; ph1.y = h3;
    __nv_bfloat162 pl0; pl0.x = l0; pl0.y = l1;
    __nv_bfloat162 pl1; pl1.x = l2; pl1.y = l3;
    *(__nv_bfloat162*)(hi + i)     = ph0;
    *(__nv_bfloat162*)(hi + i + 2) = ph1;
    *(__nv_bfloat162*)(lo + i)     = pl0;
    *(__nv_bfloat162*)(lo + i + 2) = pl1;
}

// ---------------------------------------------------------------------------
// gemm_bf16: C[M,N] fp32 = A[M,K] @ B[N,K]^T  with A,B given as (hi,lo) bf16.
// 3xBF16: acc += aHi*bHi + aHi*bLo + aLo*bHi  (wmma 16x16x16, fp32 acc)
// Tiles 128x128x32, 256 threads, 2-stage cp.async double buffer.
// Stage = 4 tiles (Ahi, Alo, Bhi, Blo), each 128 x 32 bf16 padded to ld 40.
// ---------------------------------------------------------------------------
#define GB_LDA   40
#define GB_TILE  (128 * GB_LDA)           // 5120 bf16
#define GB_STAGE (4 * GB_TILE)            // 20480 bf16 = 40960 B
#define GB_SMEM_BYTES (2 * GB_STAGE * 2)  // 81920 B

__device__ __forceinline__ void stageb(bf16* dst, const bf16* g, int ldg, int tid) {
    #pragma unroll
    for (int i = 0; i < 2; i++) {
        int id  = tid + 256 * i;          // 512 slots: 128 rows x 4 segs of 8 bf16
        int row = id >> 2, seg = id & 3;
        cp16(dst + row * GB_LDA + seg * 8, g + (long long)row * ldg + seg * 8);
    }
}

__global__ __launch_bounds__(256)
void gemm_bf16(const bf16* __restrict__ Ahi, const bf16* __restrict__ Alo,
               const bf16* __restrict__ Bhi, const bf16* __restrict__ Blo,
               float* __restrict__ C, int M, int N, int K)
{
    extern __shared__ bf16 gsmb[];

    const int tid  = threadIdx.x;
    const int warp = tid >> 5;
    const int bm   = blockIdx.y * 128;
    const int bn   = blockIdx.x * 128;
    const int wm   = (warp >> 1) * 32;    // 4 warps in m, 2 frags each
    const int wn   = (warp & 1) * 64;     // 2 warps in n, 4 frags each

    const bf16* gAh = Ahi + (long long)bm * K;
    const bf16* gAl = Alo + (long long)bm * K;
    const bf16* gBh = Bhi + (long long)bn * K;
    const bf16* gBl = Blo + (long long)bn * K;

    wmma::fragment<wmma::accumulator, 16, 16, 16, float> acc[2][4];
    #pragma unroll
    for (int i = 0; i < 2; i++)
        #pragma unroll
        for (int j = 0; j < 4; j++)
            wmma::fill_fragment(acc[i][j], 0.0f);

    const int KT = K >> 5;                // BK = 32

    // Prologue: stage 0
    {
        bf16* st = gsmb;
        stageb(st,               gAh, K, tid);
        stageb(st + GB_TILE,     gAl, K, tid);
        stageb(st + 2 * GB_TILE, gBh, K, tid);
        stageb(st + 3 * GB_TILE, gBl, K, tid);
        CP_COMMIT();
    }

    for (int kt = 0; kt < KT; kt++) {
        if (kt + 1 < KT) {
            bf16* st = gsmb + ((kt + 1) & 1) * GB_STAGE;
            long long off = (long long)(kt + 1) * 32;
            stageb(st,               gAh + off, K, tid);
            stageb(st + GB_TILE,     gAl + off, K, tid);
            stageb(st + 2 * GB_TILE, gBh + off, K, tid);
            stageb(st + 3 * GB_TILE, gBl + off, K, tid);
            CP_COMMIT();
            asm volatile("cp.async.wait_group 1;\n" ::: "memory");
        } else {
            asm volatile("cp.async.wait_group 0;\n" ::: "memory");
        }
        __syncthreads();

        const bf16* Ash = gsmb + (kt & 1) * GB_STAGE;
        const bf16* Asl = Ash + GB_TILE;
        const bf16* Bsh = Ash + 2 * GB_TILE;
        const bf16* Bsl = Ash + 3 * GB_TILE;

        #pragma unroll
        for (int kk = 0; kk < 32; kk += 16) {
            wmma::fragment<wmma::matrix_a, 16, 16, 16, bf16, wmma::row_major> aHi[2], aLo[2];
            wmma::fragment<wmma::matrix_b, 16, 16, 16, bf16, wmma::col_major> bHi[4], bLo[4];
            #pragma unroll
            for (int i = 0; i < 2; i++) {
                wmma::load_matrix_sync(aHi[i], Ash + (wm + 16 * i) * GB_LDA + kk, GB_LDA);
                wmma::load_matrix_sync(aLo[i], Asl + (wm + 16 * i) * GB_LDA + kk, GB_LDA);
            }
            #pragma unroll
            for (int j = 0; j < 4; j++) {
                wmma::load_matrix_sync(bHi[j], Bsh + (wn + 16 * j) * GB_LDA + kk, GB_LDA);
                wmma::load_matrix_sync(bLo[j], Bsl + (wn + 16 * j) * GB_LDA + kk, GB_LDA);
            }
            #pragma unroll
            for (int i = 0; i < 2; i++)
                #pragma unroll
                for (int j = 0; j < 4; j++) {
                    wmma::mma_sync(acc[i][j], aHi[i], bLo[j], acc[i][j]);
                    wmma::mma_sync(acc[i][j], aLo[i], bHi[j], acc[i][j]);
                    wmma::mma_sync(acc[i][j], aHi[i], bHi[j], acc[i][j]);
                }
        }
        __syncthreads();
    }

    #pragma unroll
    for (int i = 0; i < 2; i++)
        #pragma unroll
        for (int j = 0; j < 4; j++)
            wmma::store_matrix_sync(&C[(long long)(bm + wm + 16 * i) * N + bn + wn + 16 * j],
                                    acc[i][j], N, wmma::mem_row_major);
}

// ---------------------------------------------------------------------------
// Flash attention, 3xBF16, single pass, max-free.
// Per CTA: 128 q-rows of one (b,h); K/V tiles 64 wide, cp.async double-buffered.
// 512 threads, 16 warps, warp tile 16x32.
// Writes UNNORMALIZED p=exp(s) fp32 to att (streaming stores);
// accumulates L and y'=p@V; epilogue writes y=y'/L as (hi,lo) bf16 and 1/L.
// smem layout (bytes):
//   Qhi [128][72]b  @      0 (18432)
//   Qlo [128][72]b  @  18432 (18432)
//   Ss  [128][68]f  @  36864 (34816)    p fp32 staging
//   Phi [128][72]b  @  71680 (18432)
//   Plo [128][72]b  @  90112 (18432)
//   KV  [2][4][64][72]b @ 108544 (73728)   order per buf: Khi,Klo,Vhi,Vlo
//   Lrow[128]f      @ 182272 (512)
// total 182784
// ---------------------------------------------------------------------------
#define FLB_LDB 72
#define FLB_LDS 68
#define FLB_QHI 0
#define FLB_QLO 18432
#define FLB_SS  36864
#define FLB_P_HI 71680
#define FLB_P_LO 90112
#define FLB_KV  108544
#define FLB_KVTILE (64 * FLB_LDB * 2)      // 9216 B per tile
#define FLB_KVBUF  (4 * FLB_KVTILE)        // 36864 B per buffer
#define FLB_LROW 182272
#define FLB_SMEM_BYTES 182784
#define FLB_THREADS 512

__global__ __launch_bounds__(FLB_THREADS)
void attn_flash_bf16(const bf16* __restrict__ qh, const bf16* __restrict__ ql,
                     float* __restrict__ att,
                     bf16* __restrict__ yhi, bf16* __restrict__ ylo,
                     float* __restrict__ invLout)
{
    extern __shared__ char smc[];
    bf16*  Qhi  = (bf16*)(smc + FLB_QHI);
    bf16*  Qlo  = (bf16*)(smc + FLB_QLO);
    float* Ss   = (float*)(smc + FLB_SS);
    bf16*  Phi  = (bf16*)(smc + FLB_P_HI);
    bf16*  Plo  = (bf16*)(smc + FLB_P_LO);
    float* Lrow = (float*)(smc + FLB_LROW);

    const int tid = threadIdx.x, warp = tid >> 5, lane = tid & 31;
    const int bh = blockIdx.y, b = bh >> 4, h = bh & 15;
    const int s0 = blockIdx.x * 128;

    const long long qoff = ((long long)(b * PS + s0)) * (3 * PD) + h * PHD;
    const long long koff = ((long long)b * PS) * (3 * PD) + PD + h * PHD;
    const long long voff = ((long long)b * PS) * (3 * PD) + 2 * PD + h * PHD;

    if (tid < 128) Lrow[tid] = 0.0f;

    // Q tiles (hi and lo): 128 rows x 64 bf16 = 8 segs of 8
    #pragma unroll
    for (int i = 0; i < 2; i++) {
        int id = tid + FLB_THREADS * i;   // 1024 slots
        int r = id >> 3, seg = id & 7;
        cp16(Qhi + r * FLB_LDB + seg * 8, qh + qoff + (long long)r * (3 * PD) + seg * 8);
    }
    #pragma unroll
    for (int i = 0; i < 2; i++) {
        int id = tid + FLB_THREADS * i;
        int r = id >> 3, seg = id & 7;
        cp16(Qlo + r * FLB_LDB + seg * 8, ql + qoff + (long long)r * (3 * PD) + seg * 8);
    }

    // Stage K/V buffer 0: 4 tiles of 64x64 bf16, 512 threads = one pass per tile
    {
        char* buf = smc + FLB_KV;
        int r = tid >> 3, seg = tid & 7;
        long long go = (long long)r * (3 * PD) + seg * 8;
        cp16((bf16*)(buf)                  + r * FLB_LDB + seg * 8, qh + koff + go);
        cp16((bf16*)(buf + FLB_KVTILE)     + r * FLB_LDB + seg * 8, ql + koff + go);
        cp16((bf16*)(buf + 2 * FLB_KVTILE) + r * FLB_LDB + seg * 8, qh + voff + go);
        cp16((bf16*)(buf + 3 * FLB_KVTILE) + r * FLB_LDB + seg * 8, ql + voff + go);
        CP_COMMIT();
    }

    const int wm = (warp >> 1) * 16;      // 8 row groups (128 rows)
    const int wn = (warp & 1) * 32;       // 2 col groups (64 cols)
    wmma::fragment<wmma::accumulator, 16, 16, 16, float> accY[2];
    wmma::fill_fragment(accY[0], 0.0f);
    wmma::fill_fragment(accY[1], 0.0f);

    const int pr  = tid >> 2;             // owned p-row (0..127)
    const int pc0 = (tid & 3) * 16;       // first of 16 owned cols
    const size_t attRow0 = (size_t)bh * PS + s0;

    const int NT = PS / 64;               // 32 iterations
    for (int nt = 0; nt < NT; nt++) {
        char* bufc = smc + FLB_KV + (nt & 1) * FLB_KVBUF;
        const bf16* Khi = (const bf16*)(bufc);
        const bf16* Klo = (const bf16*)(bufc + FLB_KVTILE);
        const bf16* Vhi = (const bf16*)(bufc + 2 * FLB_KVTILE);
        const bf16* Vlo = (const bf16*)(bufc + 3 * FLB_KVTILE);

        if (nt + 1 < NT) {
            char* bufn = smc + FLB_KV + ((nt + 1) & 1) * FLB_KVBUF;
            int r = tid >> 3, seg = tid & 7;
            long long go = (long long)(nt + 1) * 64 * (3 * PD) + (long long)r * (3 * PD) + seg * 8;
            cp16((bf16*)(bufn)                  + r * FLB_LDB + seg * 8, qh + koff + go);
            cp16((bf16*)(bufn + FLB_KVTILE)     + r * FLB_LDB + seg * 8, ql + koff + go);
            cp16((bf16*)(bufn + 2 * FLB_KVTILE) + r * FLB_LDB + seg * 8, qh + voff + go);
            cp16((bf16*)(bufn + 3 * FLB_KVTILE) + r * FLB_LDB + seg * 8, ql + voff + go);
            CP_COMMIT();
            asm volatile("cp.async.wait_group 1;\n" ::: "memory");
        } else {
            asm volatile("cp.async.wait_group 0;\n" ::: "memory");
        }
        __syncthreads();

        // scores = Q @ K^T (3xBF16), then p = exp(0.125*s) in-register
        {
            wmma::fragment<wmma::accumulator, 16, 16, 16, float> accS[2];
            wmma::fill_fragment(accS[0], 0.0f);
            wmma::fill_fragment(accS[1], 0.0f);
            #pragma unroll
            for (int kk = 0; kk < 64; kk += 16) {
                wmma::fragment<wmma::matrix_a, 16, 16, 16, bf16, wmma::row_major> aHi, aLo;
                wmma::load_matrix_sync(aHi, Qhi + wm * FLB_LDB + kk, FLB_LDB);
                wmma::load_matrix_sync(aLo, Qlo + wm * FLB_LDB + kk, FLB_LDB);
                #pragma unroll
                for (int j = 0; j < 2; j++) {
                    wmma::fragment<wmma::matrix_b, 16, 16, 16, bf16, wmma::col_major> bHi, bLo;
                    wmma::load_matrix_sync(bHi, Khi + (wn + 16 * j) * FLB_LDB + kk, FLB_LDB);
                    wmma::load_matrix_sync(bLo, Klo + (wn + 16 * j) * FLB_LDB + kk, FLB_LDB);
                    wmma::mma_sync(accS[j], aHi, bLo, accS[j]);
                    wmma::mma_sync(accS[j], aLo, bHi, accS[j]);
                    wmma::mma_sync(accS[j], aHi, bHi, accS[j]);
                }
            }
            #pragma unroll
            for (int j = 0; j < 2; j++)
                #pragma unroll
                for (int t = 0; t < accS[j].num_elements; t++)
                    accS[j].x[t] = __expf(accS[j].x[t] * 0.125f);
            wmma::store_matrix_sync(Ss + wm * FLB_LDS + wn,      accS[0], FLB_LDS, wmma::mem_row_major);
            wmma::store_matrix_sync(Ss + wm * FLB_LDS + wn + 16, accS[1], FLB_LDS, wmma::mem_row_major);
        }
        __syncthreads();

        // write unnormalized att (fp32, streaming), split p -> bf16 hi/lo, row sums
        {
            const int n0 = nt * 64;
            float pv[16];
            float sum = 0.0f;
            #pragma unroll
            for (int t = 0; t < 16; t++) {
                pv[t] = Ss[pr * FLB_LDS + pc0 + t];
                sum += pv[t];
            }
            float4* dst = (float4*)(att + (attRow0 + pr) * PS + n0 + pc0);
            #pragma unroll
            for (int q = 0; q < 4; q++)
                __stcs(dst + q, make_float4(pv[4 * q], pv[4 * q + 1], pv[4 * q + 2], pv[4 * q + 3]));

            #pragma unroll
            for (int t = 0; t < 16; t += 2) {
                bf16 h0, l0, h1, l1;
                split2(pv[t],     h0, l0);
                split2(pv[t + 1], h1, l1);
                __nv_bfloat162 ph; ph.x = h0; ph.y = h1;
                __nv_bfloat162 pl; pl.x = l0; pl.y = l1;
                *(__nv_bfloat162*)(Phi + pr * FLB_LDB + pc0 + t) = ph;
                *(__nv_bfloat162*)(Plo + pr * FLB_LDB + pc0 + t) = pl;
            }

            sum += __shfl_xor_sync(0xffffffffu, sum, 1);
            sum += __shfl_xor_sync(0xffffffffu, sum, 2);
            if ((lane & 3) == 0) Lrow[pr] += sum;
        }
        __syncthreads();

        // y' += p @ V   (3xBF16)
        #pragma unroll
        for (int kk = 0; kk < 64; kk += 16) {
            wmma::fragment<wmma::matrix_a, 16, 16, 16, bf16, wmma::row_major> aHi, aLo;
            wmma::load_matrix_sync(aHi, Phi + wm * FLB_LDB + kk, FLB_LDB);
            wmma::load_matrix_sync(aLo, Plo + wm * FLB_LDB + kk, FLB_LDB);
            #pragma unroll
            for (int j = 0; j < 2; j++) {
                wmma::fragment<wmma::matrix_b, 16, 16, 16, bf16, wmma::row_major> bHi, bLo;
                wmma::load_matrix_sync(bHi, Vhi + kk * FLB_LDB + wn + 16 * j, FLB_LDB);
                wmma::load_matrix_sync(bLo, Vlo + kk * FLB_LDB + wn + 16 * j, FLB_LDB);
                wmma::mma_sync(accY[j], aHi, bLo, accY[j]);
                wmma::mma_sync(accY[j], aLo, bHi, accY[j]);
                wmma::mma_sync(accY[j], aHi, bHi, accY[j]);
            }
        }
        __syncthreads();
    }

    // Epilogue: y' -> Ss staging, scale by 1/L, write y as (hi,lo) bf16
    wmma::store_matrix_sync(Ss + wm * FLB_LDS + wn,      accY[0], FLB_LDS, wmma::mem_row_major);
    wmma::store_matrix_sync(Ss + wm * FLB_LDS + wn + 16, accY[1], FLB_LDS, wmma::mem_row_major);
    __syncthreads();

    if (tid < 128) invLout[attRow0 + tid] = 1.0f / Lrow[tid];

    {
        const int r = tid >> 2, c0 = (tid & 3) * 16;
        const float inv = 1.0f / Lrow[r];
        long long ybase = ((long long)(b * PS + s0 + r)) * PD + h * PHD + c0;
        #pragma unroll
        for (int t = 0; t < 16; t += 2) {
            float v0 = Ss[r * FLB_LDS + c0 + t]     * inv;
            float v1 = Ss[r * FLB_LDS + c0 + t + 1] * inv;
            bf16 h0, l0, h1, l1;
            split2(v0, h0, l0);
            split2(v1, h1, l1);
            __nv_bfloat162 ph; ph.x = h0; ph.y = h1;
            __nv_bfloat162 pl; pl.x = l0; pl.y = l1;
            *(__nv_bfloat162*)(yhi + ybase + t) = ph;
            *(__nv_bfloat162*)(ylo + ybase + t) = pl;
        }
    }
}

// ---------------------------------------------------------------------------
// att fixup: scale each row of att by its 1/L. One block per row.
// Streaming load/store: att is touched exactly once here, never again.
// ---------------------------------------------------------------------------
__global__ __launch_bounds__(512)
void att_scale(float* __restrict__ att, const float* __restrict__ invL)
{
    const size_t row = blockIdx.x;
    const float s = invL[row];
    float4* p = (float4*)(att + row * PS);
    float4 v = __ldcs(p + threadIdx.x);
    v.x *= s; v.y *= s; v.z *= s; v.w *= s;
    __stcs(p + threadIdx.x, v);
}

__global__ __launch_bounds__(256)
void add_bias(float* __restrict__ y, const float* __restrict__ bias, long long n)
{
    long long i = (long long)blockIdx.x * blockDim.x + threadIdx.x;
    if (i < n) y[i] += bias[i & (PD - 1)];
}

// ---------------------------------------------------------------------------
extern "C" void kernel_launch(void* const* d_in, const int* in_sizes, int n_in,
                              void* d_out, int out_size)
{
    const float* x     = (const float*)d_in[0];   // [B,S,D]
    const float* Wattn = (const float*)d_in[1];   // [3D, D]
    const float* Wproj = (const float*)d_in[2];   // [D, D]
    const float* bproj = (const float*)d_in[3];   // [D]
    float* out = (float*)d_out;

    float *qkv, *invL;
    bf16 *xhi, *xlo, *Wahi, *Walo, *Wphi, *Wplo, *qkvhi, *qkvlo, *yhi, *ylo;
    cudaGetSymbolAddress((void**)&qkv,   g_qkv);
    cudaGetSymbolAddress((void**)&invL,  g_invL);
    cudaGetSymbolAddress((void**)&xhi,   g_xhi);
    cudaGetSymbolAddress((void**)&xlo,   g_xlo);
    cudaGetSymbolAddress((void**)&Wahi,  g_Wahi);
    cudaGetSymbolAddress((void**)&Walo,  g_Walo);
    cudaGetSymbolAddress((void**)&Wphi,  g_Wphi);
    cudaGetSymbolAddress((void**)&Wplo,  g_Wplo);
    cudaGetSymbolAddress((void**)&qkvhi, g_qkvhi);
    cudaGetSymbolAddress((void**)&qkvlo, g_qkvlo);
    cudaGetSymbolAddress((void**)&yhi,   g_yhi);
    cudaGetSymbolAddress((void**)&ylo,   g_ylo);

    const long long yElems   = (long long)PB * PS * PD;        // 4,194,304
    const long long attElems = (long long)PB * PH * PS * PS;   // 134,217,728

    float* attOut;
    if ((long long)out_size >= yElems + attElems) {
        attOut = out + yElems;                                 // (y, att) concat
    } else {
        cudaGetSymbolAddress((void**)&attOut, g_att_scratch);
    }

    cudaFuncSetAttribute(gemm_bf16, cudaFuncAttributeMaxDynamicSharedMemorySize,
                         GB_SMEM_BYTES);
    cudaFuncSetAttribute(attn_flash_bf16, cudaFuncAttributeMaxDynamicSharedMemorySize,
                         FLB_SMEM_BYTES);

    const long long nX  = (long long)PB * PS * PD;       // 8,388,608
    const long long nWa = (long long)3 * PD * PD;        // 3,145,728
    const long long nWp = (long long)PD * PD;            // 1,048,576
    const long long nQ  = (long long)PB * PS * 3 * PD;   // 25,165,824

    // 0) split inputs to (hi, lo) bf16
    split_bf16<<<(unsigned)(nX  / 1024), 256>>>(x,     xhi,  xlo,  nX);
    split_bf16<<<(unsigned)(nWa / 1024), 256>>>(Wattn, Wahi, Walo, nWa);
    split_bf16<<<(unsigned)(nWp / 1024), 256>>>(Wproj, Wphi, Wplo, nWp);

    // 1) qkv = x @ W_attn^T : [4096, 3072] fp32
    gemm_bf16<<<dim3(3 * PD / 128, PB * PS / 128), 256, GB_SMEM_BYTES>>>(
        xhi, xlo, Wahi, Walo, qkv, PB * PS, 3 * PD, PD);

    // 2) split qkv
    split_bf16<<<(unsigned)(nQ / 1024), 256>>>(qkv, qkvhi, qkvlo, nQ);

    // 3) flash: unnormalized att + L + y as bf16 hi/lo
    attn_flash_bf16<<<dim3(PS / 128, PB * PH), FLB_THREADS, FLB_SMEM_BYTES>>>(
        qkvhi, qkvlo, attOut, yhi, ylo, invL);

    // 4) normalize att rows
    att_scale<<<PB * PH * PS, 512>>>(attOut, invL);

    // 5) out_y = y @ W_proj^T
    gemm_bf16<<<dim3(PD / 128, PB * PS / 128), 256, GB_SMEM_BYTES>>>(
        yhi, ylo, Wphi, Wplo, out, PB * PS, PD, PD);

    // 6) + b_proj
    add_bias<<<(unsigned)((yElems + 255) / 256), 256>>>(out, bproj, yElems);
}

// round 14
// speedup vs baseline: 2.3022x; 1.0621x over previous
#include <cuda_runtime.h>
#include <cuda_bf16.h>
#include <mma.h>

using namespace nvcuda;
typedef __nv_bfloat16 bf16;

#define PB 2
#define PS 2048
#define PD 1024
#define PH 16
#define PHD 64

// ---------------------------------------------------------------------------
// Scratch (__device__ globals; no allocation allowed)
// ---------------------------------------------------------------------------
__device__ bf16  g_xhi [(size_t)PB * PS * PD];
__device__ bf16  g_xlo [(size_t)PB * PS * PD];
__device__ bf16  g_Wahi[(size_t)3 * PD * PD];
__device__ bf16  g_Walo[(size_t)3 * PD * PD];
__device__ bf16  g_Wphi[(size_t)PD * PD];
__device__ bf16  g_Wplo[(size_t)PD * PD];
__device__ bf16  g_qkvhi[(size_t)PB * PS * 3 * PD];
__device__ bf16  g_qkvlo[(size_t)PB * PS * 3 * PD];
__device__ bf16  g_yhi [(size_t)PB * PS * PD];
__device__ bf16  g_ylo [(size_t)PB * PS * PD];
__device__ float g_invL[(size_t)PB * PH * PS];
__device__ float g_att_scratch[(size_t)PB * PH * PS * PS];  // fallback

// cp.async helpers
__device__ __forceinline__ void cp16(void* smem, const void* gmem) {
    unsigned s = (unsigned)__cvta_generic_to_shared(smem);
    asm volatile("cp.async.cg.shared.global [%0], [%1], 16;\n" :: "r"(s), "l"(gmem));
}
#define CP_COMMIT() asm volatile("cp.async.commit_group;\n" ::: "memory")

__device__ __forceinline__ void split2(float x, bf16& hi, bf16& lo) {
    hi = __float2bfloat16_rn(x);
    lo = __float2bfloat16_rn(x - __bfloat162float(hi));
}

// ---------------------------------------------------------------------------
// split_bf16: fp32 -> (hi, lo) bf16 arrays. n must be a multiple of 4.
// ---------------------------------------------------------------------------
__global__ __launch_bounds__(256)
void split_bf16(const float* __restrict__ src, bf16* __restrict__ hi,
                bf16* __restrict__ lo, long long n)
{
    long long i = ((long long)blockIdx.x * 256 + threadIdx.x) * 4;
    if (i >= n) return;
    float4 v = *(const float4*)(src + i);
    bf16 h0, l0, h1, l1, h2, l2, h3, l3;
    split2(v.x, h0, l0); split2(v.y, h1, l1);
    split2(v.z, h2, l2); split2(v.w, h3, l3);
    __nv_bfloat162 ph0; ph0.x = h0; ph0.y = h1;
    __nv_bfloat162 ph1; ph1.x = h2; ph1.y = h3;
    __nv_bfloat162 pl0; pl0.x = l0; pl0.y = l1;
    __nv_bfloat162 pl1; pl1.x = l2; pl1.y = l3;
    *(__nv_bfloat162*)(hi + i)     = ph0;
    *(__nv_bfloat162*)(hi + i + 2) = ph1;
    *(__nv_bfloat162*)(lo + i)     = pl0;
    *(__nv_bfloat162*)(lo + i + 2) = pl1;
}

// ---------------------------------------------------------------------------
// gemm_bf16: C[M,N] = A[M,K] @ B[N,K]^T  with A,B given as (hi,lo) bf16.
// 3xBF16: acc += aHi*bHi + aHi*bLo + aLo*bHi  (wmma 16x16x16, fp32 acc)
// Tiles 128x128x32, 256 threads (<=128 regs, 2 CTAs/SM), 2-stage cp.async.
// MODE 0: fp32 C.  MODE 1: split C to (hi,lo) bf16.  MODE 2: fp32 C + bias.
// Modes 1/2 stage the tile through smem.
// ---------------------------------------------------------------------------
#define GB_LDA   40
#define GB_TILE  (128 * GB_LDA)           // 5120 bf16
#define GB_STAGE (4 * GB_TILE)            // 20480 bf16 = 40960 B
#define GB_SMEM_BYTES (2 * GB_STAGE * 2)  // 81920 B  (>= 65536 B staging)

__device__ __forceinline__ void stageb(bf16* dst, const bf16* g, int ldg, int tid) {
    #pragma unroll
    for (int i = 0; i < 2; i++) {
        int id  = tid + 256 * i;          // 512 slots: 128 rows x 4 segs of 8 bf16
        int row = id >> 2, seg = id & 3;
        cp16(dst + row * GB_LDA + seg * 8, g + (long long)row * ldg + seg * 8);
    }
}

template <int MODE>
__global__ __launch_bounds__(256, 2)
void gemm_bf16(const bf16* __restrict__ Ahi, const bf16* __restrict__ Alo,
               const bf16* __restrict__ Bhi, const bf16* __restrict__ Blo,
               float* __restrict__ C,
               bf16* __restrict__ Chi, bf16* __restrict__ Clo,
               const float* __restrict__ bias,
               int M, int N, int K)
{
    extern __shared__ bf16 gsmb[];

    const int tid  = threadIdx.x;
    const int warp = tid >> 5;
    const int bm   = blockIdx.y * 128;
    const int bn   = blockIdx.x * 128;
    const int wm   = (warp >> 1) * 32;    // 4 warps in m, 2 frags each
    const int wn   = (warp & 1) * 64;     // 2 warps in n, 4 frags each

    const bf16* gAh = Ahi + (long long)bm * K;
    const bf16* gAl = Alo + (long long)bm * K;
    const bf16* gBh = Bhi + (long long)bn * K;
    const bf16* gBl = Blo + (long long)bn * K;

    wmma::fragment<wmma::accumulator, 16, 16, 16, float> acc[2][4];
    #pragma unroll
    for (int i = 0; i < 2; i++)
        #pragma unroll
        for (int j = 0; j < 4; j++)
            wmma::fill_fragment(acc[i][j], 0.0f);

    const int KT = K >> 5;                // BK = 32

    // Prologue: stage 0
    {
        bf16* st = gsmb;
        stageb(st,               gAh, K, tid);
        stageb(st + GB_TILE,     gAl, K, tid);
        stageb(st + 2 * GB_TILE, gBh, K, tid);
        stageb(st + 3 * GB_TILE, gBl, K, tid);
        CP_COMMIT();
    }

    for (int kt = 0; kt < KT; kt++) {
        if (kt + 1 < KT) {
            bf16* st = gsmb + ((kt + 1) & 1) * GB_STAGE;
            long long off = (long long)(kt + 1) * 32;
            stageb(st,               gAh + off, K, tid);
            stageb(st + GB_TILE,     gAl + off, K, tid);
            stageb(st + 2 * GB_TILE, gBh + off, K, tid);
            stageb(st + 3 * GB_TILE, gBl + off, K, tid);
            CP_COMMIT();
            asm volatile("cp.async.wait_group 1;\n" ::: "memory");
        } else {
            asm volatile("cp.async.wait_group 0;\n" ::: "memory");
        }
        __syncthreads();

        const bf16* Ash = gsmb + (kt & 1) * GB_STAGE;
        const bf16* Asl = Ash + GB_TILE;
        const bf16* Bsh = Ash + 2 * GB_TILE;
        const bf16* Bsl = Ash + 3 * GB_TILE;

        #pragma unroll
        for (int kk = 0; kk < 32; kk += 16) {
            wmma::fragment<wmma::matrix_a, 16, 16, 16, bf16, wmma::row_major> aHi[2], aLo[2];
            wmma::fragment<wmma::matrix_b, 16, 16, 16, bf16, wmma::col_major> bHi[4], bLo[4];
            #pragma unroll
            for (int i = 0; i < 2; i++) {
                wmma::load_matrix_sync(aHi[i], Ash + (wm + 16 * i) * GB_LDA + kk, GB_LDA);
                wmma::load_matrix_sync(aLo[i], Asl + (wm + 16 * i) * GB_LDA + kk, GB_LDA);
            }
            #pragma unroll
            for (int j = 0; j < 4; j++) {
                wmma::load_matrix_sync(bHi[j], Bsh + (wn + 16 * j) * GB_LDA + kk, GB_LDA);
                wmma::load_matrix_sync(bLo[j], Bsl + (wn + 16 * j) * GB_LDA + kk, GB_LDA);
            }
            #pragma unroll
            for (int i = 0; i < 2; i++)
                #pragma unroll
                for (int j = 0; j < 4; j++) {
                    wmma::mma_sync(acc[i][j], aHi[i], bLo[j], acc[i][j]);
                    wmma::mma_sync(acc[i][j], aLo[i], bHi[j], acc[i][j]);
                    wmma::mma_sync(acc[i][j], aHi[i], bHi[j], acc[i][j]);
                }
        }
        __syncthreads();
    }

    if (MODE == 0) {
        #pragma unroll
        for (int i = 0; i < 2; i++)
            #pragma unroll
            for (int j = 0; j < 4; j++)
                wmma::store_matrix_sync(&C[(long long)(bm + wm + 16 * i) * N + bn + wn + 16 * j],
                                        acc[i][j], N, wmma::mem_row_major);
    } else {
        // Stage fp32 tile in smem (64KB <= 80KB)
        float* stage = (float*)gsmb;      // 128 x 128 fp32
        #pragma unroll
        for (int i = 0; i < 2; i++)
            #pragma unroll
            for (int j = 0; j < 4; j++)
                wmma::store_matrix_sync(stage + (wm + 16 * i) * 128 + wn + 16 * j,
                                        acc[i][j], 128, wmma::mem_row_major);
        __syncthreads();
        if (MODE == 1) {
            // split to bf16 hi/lo
            #pragma unroll
            for (int it = 0; it < 32; it++) {
                int e = it * 512 + tid * 2;   // 16384 elems, 2 per thread per pass
                int r = e >> 7, c = e & 127;
                float v0 = stage[e], v1 = stage[e + 1];
                bf16 h0, l0, h1, l1;
                split2(v0, h0, l0);
                split2(v1, h1, l1);
                __nv_bfloat162 ph; ph.x = h0; ph.y = h1;
                __nv_bfloat162 pl; pl.x = l0; pl.y = l1;
                long long o = (long long)(bm + r) * N + bn + c;
                *(__nv_bfloat162*)(Chi + o) = ph;
                *(__nv_bfloat162*)(Clo + o) = pl;
            }
        } else {
            // MODE 2: fp32 + bias, float4 stores
            #pragma unroll
            for (int it = 0; it < 16; it++) {
                int e = it * 1024 + tid * 4;  // 16384 elems, 4 per thread per pass
                int r = e >> 7, c = e & 127;
                float4 v = *(float4*)(stage + e);
                float4 bb = *(const float4*)(bias + bn + c);
                v.x += bb.x; v.y += bb.y; v.z += bb.z; v.w += bb.w;
                *(float4*)(C + (long long)(bm + r) * N + bn + c) = v;
            }
        }
    }
}

// ---------------------------------------------------------------------------
// Flash attention, 3xBF16, single pass, max-free.
// Per CTA: 128 q-rows of one (b,h); K/V tiles 64 wide, cp.async double-buffered.
// 512 threads, 16 warps, warp tile 16x32.
// Writes UNNORMALIZED p=exp(s) fp32 to att (streaming stores);
// accumulates L and y'=p@V; epilogue writes y=y'/L as (hi,lo) bf16 and 1/L.
// ---------------------------------------------------------------------------
#define FLB_LDB 72
#define FLB_LDS 68
#define FLB_QHI 0
#define FLB_QLO 18432
#define FLB_SS  36864
#define FLB_P_HI 71680
#define FLB_P_LO 90112
#define FLB_KV  108544
#define FLB_KVTILE (64 * FLB_LDB * 2)      // 9216 B per tile
#define FLB_KVBUF  (4 * FLB_KVTILE)        // 36864 B per buffer
#define FLB_LROW 182272
#define FLB_SMEM_BYTES 182784
#define FLB_THREADS 512

__global__ __launch_bounds__(FLB_THREADS)
void attn_flash_bf16(const bf16* __restrict__ qh, const bf16* __restrict__ ql,
                     float* __restrict__ att,
                     bf16* __restrict__ yhi, bf16* __restrict__ ylo,
                     float* __restrict__ invLout)
{
    extern __shared__ char smc[];
    bf16*  Qhi  = (bf16*)(smc + FLB_QHI);
    bf16*  Qlo  = (bf16*)(smc + FLB_QLO);
    float* Ss   = (float*)(smc + FLB_SS);
    bf16*  Phi  = (bf16*)(smc + FLB_P_HI);
    bf16*  Plo  = (bf16*)(smc + FLB_P_LO);
    float* Lrow = (float*)(smc + FLB_LROW);

    const int tid = threadIdx.x, warp = tid >> 5, lane = tid & 31;
    const int bh = blockIdx.y, b = bh >> 4, h = bh & 15;
    const int s0 = blockIdx.x * 128;

    const long long qoff = ((long long)(b * PS + s0)) * (3 * PD) + h * PHD;
    const long long koff = ((long long)b * PS) * (3 * PD) + PD + h * PHD;
    const long long voff = ((long long)b * PS) * (3 * PD) + 2 * PD + h * PHD;

    if (tid < 128) Lrow[tid] = 0.0f;

    // Q tiles (hi and lo): 128 rows x 64 bf16 = 8 segs of 8
    #pragma unroll
    for (int i = 0; i < 2; i++) {
        int id = tid + FLB_THREADS * i;   // 1024 slots
        int r = id >> 3, seg = id & 7;
        cp16(Qhi + r * FLB_LDB + seg * 8, qh + qoff + (long long)r * (3 * PD) + seg * 8);
    }
    #pragma unroll
    for (int i = 0; i < 2; i++) {
        int id = tid + FLB_THREADS * i;
        int r = id >> 3, seg = id & 7;
        cp16(Qlo + r * FLB_LDB + seg * 8, ql + qoff + (long long)r * (3 * PD) + seg * 8);
    }

    // Stage K/V buffer 0: 4 tiles of 64x64 bf16, 512 threads = one pass per tile
    {
        char* buf = smc + FLB_KV;
        int r = tid >> 3, seg = tid & 7;
        long long go = (long long)r * (3 * PD) + seg * 8;
        cp16((bf16*)(buf)                  + r * FLB_LDB + seg * 8, qh + koff + go);
        cp16((bf16*)(buf + FLB_KVTILE)     + r * FLB_LDB + seg * 8, ql + koff + go);
        cp16((bf16*)(buf + 2 * FLB_KVTILE) + r * FLB_LDB + seg * 8, qh + voff + go);
        cp16((bf16*)(buf + 3 * FLB_KVTILE) + r * FLB_LDB + seg * 8, ql + voff + go);
        CP_COMMIT();
    }

    const int wm = (warp >> 1) * 16;      // 8 row groups (128 rows)
    const int wn = (warp & 1) * 32;       // 2 col groups (64 cols)
    wmma::fragment<wmma::accumulator, 16, 16, 16, float> accY[2];
    wmma::fill_fragment(accY[0], 0.0f);
    wmma::fill_fragment(accY[1], 0.0f);

    const int pr  = tid >> 2;             // owned p-row (0..127)
    const int pc0 = (tid & 3) * 16;       // first of 16 owned cols
    const size_t attRow0 = (size_t)bh * PS + s0;

    const int NT = PS / 64;               // 32 iterations
    for (int nt = 0; nt < NT; nt++) {
        char* bufc = smc + FLB_KV + (nt & 1) * FLB_KVBUF;
        const bf16* Khi = (const bf16*)(bufc);
        const bf16* Klo = (const bf16*)(bufc + FLB_KVTILE);
        const bf16* Vhi = (const bf16*)(bufc + 2 * FLB_KVTILE);
        const bf16* Vlo = (const bf16*)(bufc + 3 * FLB_KVTILE);

        if (nt + 1 < NT) {
            char* bufn = smc + FLB_KV + ((nt + 1) & 1) * FLB_KVBUF;
            int r = tid >> 3, seg = tid & 7;
            long long go = (long long)(nt + 1) * 64 * (3 * PD) + (long long)r * (3 * PD) + seg * 8;
            cp16((bf16*)(bufn)                  + r * FLB_LDB + seg * 8, qh + koff + go);
            cp16((bf16*)(bufn + FLB_KVTILE)     + r * FLB_LDB + seg * 8, ql + koff + go);
            cp16((bf16*)(bufn + 2 * FLB_KVTILE) + r * FLB_LDB + seg * 8, qh + voff + go);
            cp16((bf16*)(bufn + 3 * FLB_KVTILE) + r * FLB_LDB + seg * 8, ql + voff + go);
            CP_COMMIT();
            asm volatile("cp.async.wait_group 1;\n" ::: "memory");
        } else {
            asm volatile("cp.async.wait_group 0;\n" ::: "memory");
        }
        __syncthreads();

        // scores = Q @ K^T (3xBF16), then p = exp(0.125*s) in-register
        {
            wmma::fragment<wmma::accumulator, 16, 16, 16, float> accS[2];
            wmma::fill_fragment(accS[0], 0.0f);
            wmma::fill_fragment(accS[1], 0.0f);
            #pragma unroll
            for (int kk = 0; kk < 64; kk += 16) {
                wmma::fragment<wmma::matrix_a, 16, 16, 16, bf16, wmma::row_major> aHi, aLo;
                wmma::load_matrix_sync(aHi, Qhi + wm * FLB_LDB + kk, FLB_LDB);
                wmma::load_matrix_sync(aLo, Qlo + wm * FLB_LDB + kk, FLB_LDB);
                #pragma unroll
                for (int j = 0; j < 2; j++) {
                    wmma::fragment<wmma::matrix_b, 16, 16, 16, bf16, wmma::col_major> bHi, bLo;
                    wmma::load_matrix_sync(bHi, Khi + (wn + 16 * j) * FLB_LDB + kk, FLB_LDB);
                    wmma::load_matrix_sync(bLo, Klo + (wn + 16 * j) * FLB_LDB + kk, FLB_LDB);
                    wmma::mma_sync(accS[j], aHi, bLo, accS[j]);
                    wmma::mma_sync(accS[j], aLo, bHi, accS[j]);
                    wmma::mma_sync(accS[j], aHi, bHi, accS[j]);
                }
            }
            #pragma unroll
            for (int j = 0; j < 2; j++)
                #pragma unroll
                for (int t = 0; t < accS[j].num_elements; t++)
                    accS[j].x[t] = __expf(accS[j].x[t] * 0.125f);
            wmma::store_matrix_sync(Ss + wm * FLB_LDS + wn,      accS[0], FLB_LDS, wmma::mem_row_major);
            wmma::store_matrix_sync(Ss + wm * FLB_LDS + wn + 16, accS[1], FLB_LDS, wmma::mem_row_major);
        }
        __syncthreads();

        // write unnormalized att (fp32, streaming), split p -> bf16 hi/lo, row sums
        {
            const int n0 = nt * 64;
            float pv[16];
            float sum = 0.0f;
            #pragma unroll
            for (int t = 0; t < 16; t++) {
                pv[t] = Ss[pr * FLB_LDS + pc0 + t];
                sum += pv[t];
            }
            float4* dst = (float4*)(att + (attRow0 + pr) * PS + n0 + pc0);
            #pragma unroll
            for (int q = 0; q < 4; q++)
                __stcs(dst + q, make_float4(pv[4 * q], pv[4 * q + 1], pv[4 * q + 2], pv[4 * q + 3]));

            #pragma unroll
            for (int t = 0; t < 16; t += 2) {
                bf16 h0, l0, h1, l1;
                split2(pv[t],     h0, l0);
                split2(pv[t + 1], h1, l1);
                __nv_bfloat162 ph; ph.x = h0; ph.y = h1;
                __nv_bfloat162 pl; pl.x = l0; pl.y = l1;
                *(__nv_bfloat162*)(Phi + pr * FLB_LDB + pc0 + t) = ph;
                *(__nv_bfloat162*)(Plo + pr * FLB_LDB + pc0 + t) = pl;
            }

            sum += __shfl_xor_sync(0xffffffffu, sum, 1);
            sum += __shfl_xor_sync(0xffffffffu, sum, 2);
            if ((lane & 3) == 0) Lrow[pr] += sum;
        }
        __syncthreads();

        // y' += p @ V   (3xBF16)
        #pragma unroll
        for (int kk = 0; kk < 64; kk += 16) {
            wmma::fragment<wmma::matrix_a, 16, 16, 16, bf16, wmma::row_major> aHi, aLo;
            wmma::load_matrix_sync(aHi, Phi + wm * FLB_LDB + kk, FLB_LDB);
            wmma::load_matrix_sync(aLo, Plo + wm * FLB_LDB + kk, FLB_LDB);
            #pragma unroll
            for (int j = 0; j < 2; j++) {
                wmma::fragment<wmma::matrix_b, 16, 16, 16, bf16, wmma::row_major> bHi, bLo;
                wmma::load_matrix_sync(bHi, Vhi + kk * FLB_LDB + wn + 16 * j, FLB_LDB);
                wmma::load_matrix_sync(bLo, Vlo + kk * FLB_LDB + wn + 16 * j, FLB_LDB);
                wmma::mma_sync(accY[j], aHi, bLo, accY[j]);
                wmma::mma_sync(accY[j], aLo, bHi, accY[j]);
                wmma::mma_sync(accY[j], aHi, bHi, accY[j]);
            }
        }
        __syncthreads();
    }

    // Epilogue: y' -> Ss staging, scale by 1/L, write y as (hi,lo) bf16
    wmma::store_matrix_sync(Ss + wm * FLB_LDS + wn,      accY[0], FLB_LDS, wmma::mem_row_major);
    wmma::store_matrix_sync(Ss + wm * FLB_LDS + wn + 16, accY[1], FLB_LDS, wmma::mem_row_major);
    __syncthreads();

    if (tid < 128) invLout[attRow0 + tid] = 1.0f / Lrow[tid];

    {
        const int r = tid >> 2, c0 = (tid & 3) * 16;
        const float inv = 1.0f / Lrow[r];
        long long ybase = ((long long)(b * PS + s0 + r)) * PD + h * PHD + c0;
        #pragma unroll
        for (int t = 0; t < 16; t += 2) {
            float v0 = Ss[r * FLB_LDS + c0 + t]     * inv;
            float v1 = Ss[r * FLB_LDS + c0 + t + 1] * inv;
            bf16 h0, l0, h1, l1;
            split2(v0, h0, l0);
            split2(v1, h1, l1);
            __nv_bfloat162 ph; ph.x = h0; ph.y = h1;
            __nv_bfloat162 pl; pl.x = l0; pl.y = l1;
            *(__nv_bfloat162*)(yhi + ybase + t) = ph;
            *(__nv_bfloat162*)(ylo + ybase + t) = pl;
        }
    }
}

// ---------------------------------------------------------------------------
// att fixup: scale each row of att by its 1/L. One block per row. Streaming.
// ---------------------------------------------------------------------------
__global__ __launch_bounds__(512)
void att_scale(float* __restrict__ att, const float* __restrict__ invL)
{
    const size_t row = blockIdx.x;
    const float s = invL[row];
    float4* p = (float4*)(att + row * PS);
    float4 v = __ldcs(p + threadIdx.x);
    v.x *= s; v.y *= s; v.z *= s; v.w *= s;
    __stcs(p + threadIdx.x, v);
}

// ---------------------------------------------------------------------------
extern "C" void kernel_launch(void* const* d_in, const int* in_sizes, int n_in,
                              void* d_out, int out_size)
{
    const float* x     = (const float*)d_in[0];   // [B,S,D]
    const float* Wattn = (const float*)d_in[1];   // [3D, D]
    const float* Wproj = (const float*)d_in[2];   // [D, D]
    const float* bproj = (const float*)d_in[3];   // [D]
    float* out = (float*)d_out;

    float *invL;
    bf16 *xhi, *xlo, *Wahi, *Walo, *Wphi, *Wplo, *qkvhi, *qkvlo, *yhi, *ylo;
    cudaGetSymbolAddress((void**)&invL,  g_invL);
    cudaGetSymbolAddress((void**)&xhi,   g_xhi);
    cudaGetSymbolAddress((void**)&xlo,   g_xlo);
    cudaGetSymbolAddress((void**)&Wahi,  g_Wahi);
    cudaGetSymbolAddress((void**)&Walo,  g_Walo);
    cudaGetSymbolAddress((void**)&Wphi,  g_Wphi);
    cudaGetSymbolAddress((void**)&Wplo,  g_Wplo);
    cudaGetSymbolAddress((void**)&qkvhi, g_qkvhi);
    cudaGetSymbolAddress((void**)&qkvlo, g_qkvlo);
    cudaGetSymbolAddress((void**)&yhi,   g_yhi);
    cudaGetSymbolAddress((void**)&ylo,   g_ylo);

    const long long yElems   = (long long)PB * PS * PD;        // 4,194,304
    const long long attElems = (long long)PB * PH * PS * PS;   // 134,217,728

    float* attOut;
    if ((long long)out_size >= yElems + attElems) {
        attOut = out + yElems;                                 // (y, att) concat
    } else {
        cudaGetSymbolAddress((void**)&attOut, g_att_scratch);
    }

    cudaFuncSetAttribute(gemm_bf16<1>, cudaFuncAttributeMaxDynamicSharedMemorySize,
                         GB_SMEM_BYTES);
    cudaFuncSetAttribute(gemm_bf16<2>, cudaFuncAttributeMaxDynamicSharedMemorySize,
                         GB_SMEM_BYTES);
    cudaFuncSetAttribute(attn_flash_bf16, cudaFuncAttributeMaxDynamicSharedMemorySize,
                         FLB_SMEM_BYTES);

    const long long nX  = (long long)PB * PS * PD;       // 8,388,608
    const long long nWa = (long long)3 * PD * PD;        // 3,145,728
    const long long nWp = (long long)PD * PD;            // 1,048,576

    // 0) split inputs to (hi, lo) bf16
    split_bf16<<<(unsigned)(nX  / 1024), 256>>>(x,     xhi,  xlo,  nX);
    split_bf16<<<(unsigned)(nWa / 1024), 256>>>(Wattn, Wahi, Walo, nWa);
    split_bf16<<<(unsigned)(nWp / 1024), 256>>>(Wproj, Wphi, Wplo, nWp);

    // 1) qkv = x @ W_attn^T, written directly as (hi,lo) bf16
    gemm_bf16<1><<<dim3(3 * PD / 128, PB * PS / 128), 256, GB_SMEM_BYTES>>>(
        xhi, xlo, Wahi, Walo, nullptr, qkvhi, qkvlo, nullptr, PB * PS, 3 * PD, PD);

    // 2) flash: unnormalized att + L + y as bf16 hi/lo
    attn_flash_bf16<<<dim3(PS / 128, PB * PH), FLB_THREADS, FLB_SMEM_BYTES>>>(
        qkvhi, qkvlo, attOut, yhi, ylo, invL);

    // 3) normalize att rows
    att_scale<<<PB * PH * PS, 512>>>(attOut, invL);

    // 4) out_y = y @ W_proj^T + b_proj  (fp32 out, bias fused)
    gemm_bf16<2><<<dim3(PD / 128, PB * PS / 128), 256, GB_SMEM_BYTES>>>(
        yhi, ylo, Wphi, Wplo, out, nullptr, nullptr, bproj, PB * PS, PD, PD);
}